// round 16
// baseline (speedup 1.0000x reference)
#include <cuda_runtime.h>

// FastfoodTransform: out[b,j] = S[j]*FWHT1024_stack( G ∘ permute_P( FWHT1024_stack(B∘x) ) ) + bias[j]
// BATCH=16384, IN=IN_EXT=1024, NSTACK=4, OUT=4096.
//
// R15 = R12 (cp.async x prefetch, swizzled layout-B staging, stride-36 float4
// transpose tiles, register weights, packed-f32x2 FWHT, (128,2)) restructured
// as a software pipeline with ONE __syncthreads per row:
//   sync -> prefetch x(i+2) -> FRONT(i+1) -> BACK(i)
// buf is double-buffered; the single barrier publishes stage(i), retires
// gathers(i-1), and publishes x(i+1) all at once. FRONT's v dies at staging,
// so register pressure stays in the proven ~233 envelope.

static __device__ __forceinline__ void fwht32p(float v[32]) {
    unsigned long long p[16];
    const unsigned long long M1 = 0xBF800000BF800000ULL;  // packed (-1.f,-1.f)
#pragma unroll
    for (int j = 0; j < 16; j++) {            // stage h=1 fused with pack
        float a = v[2*j], b = v[2*j+1];
        float s = a + b, d = a - b;
        asm("mov.b64 %0, {%1,%2};" : "=l"(p[j]) : "f"(s), "f"(d));
    }
#pragma unroll
    for (int hp = 1; hp < 16; hp <<= 1) {     // stages h=2,4,8,16
#pragma unroll
        for (int base = 0; base < 16; base += 2 * hp) {
#pragma unroll
            for (int r = 0; r < hp; r++) {
                unsigned long long A = p[base + r];
                unsigned long long Bp = p[base + r + hp];
                unsigned long long s, d;
                asm("add.rn.f32x2 %0, %1, %2;"     : "=l"(s) : "l"(A), "l"(Bp));
                asm("fma.rn.f32x2 %0, %1, %2, %3;" : "=l"(d) : "l"(Bp), "l"(M1), "l"(A));
                p[base + r]      = s;
                p[base + r + hp] = d;
            }
        }
    }
#pragma unroll
    for (int j = 0; j < 16; j++)
        asm("mov.b64 {%0,%1}, %2;" : "=f"(v[2*j]), "=f"(v[2*j+1]) : "l"(p[j]));
}

static __device__ __forceinline__ void cp_async16(unsigned saddr, const void* g) {
    asm volatile("cp.async.cg.shared.global [%0], [%1], 16;" :: "r"(saddr), "l"(g));
}

#define ROWS_PER_BLOCK 8

// Issue one row's x prefetch (thread t owns float4 chunks 2t, 2t+1), XOR-swizzled.
static __device__ __forceinline__ void prefetch_x(const float* __restrict__ x,
                                                  int row, int batch,
                                                  float* xb, int t)
{
    int rr = (row < batch) ? row : (batch - 1);
    const float* gx = x + (size_t)rr * 1024 + t * 8;
    unsigned sb = (unsigned)__cvta_generic_to_shared(xb);
    int c0 = 2 * t, c1 = 2 * t + 1;
    cp_async16(sb + (unsigned)((c0 ^ ((c0 >> 3) & 7)) * 16), gx);
    cp_async16(sb + (unsigned)((c1 ^ ((c1 >> 3) & 7)) * 16), gx + 4);
    asm volatile("cp.async.commit_group;" ::: "memory");
}

// FRONT: v = xs.*Bv ; FWHT bits0-4 ; T1 ; FWHT bits5-9 ; stage into bw (swizzled layout B)
static __device__ __forceinline__ void row_front(const float* __restrict__ xs,
                                                 const float* Bv,
                                                 float* tb, float* bw, int l)
{
    float v[32];
#pragma unroll
    for (int q = 0; q < 8; q++) {
        float4 xv = *reinterpret_cast<const float4*>(xs + 32 * l + 4 * (q ^ (l & 7)));
        v[4*q+0] = xv.x * Bv[4*q+0];
        v[4*q+1] = xv.y * Bv[4*q+1];
        v[4*q+2] = xv.z * Bv[4*q+2];
        v[4*q+3] = xv.w * Bv[4*q+3];
    }
    fwht32p(v);
    __syncwarp();                              // tb free (prior phase done)
    {
        float4* t4 = reinterpret_cast<float4*>(tb + 36 * l);
#pragma unroll
        for (int q = 0; q < 8; q++)
            t4[q] = make_float4(v[4*q+0], v[4*q+1], v[4*q+2], v[4*q+3]);
    }
    __syncwarp();
#pragma unroll
    for (int k = 0; k < 32; k++) v[k] = tb[36 * k + l];
    fwht32p(v);
#pragma unroll
    for (int q = 0; q < 8; q++) {              // 8x STS.128, swizzled, conflict-free
        int p = 8 * l + (q ^ (l & 7));
        *reinterpret_cast<float4*>(bw + 4 * p) =
            make_float4(v[4*q+0], v[4*q+1], v[4*q+2], v[4*q+3]);
    }
}

// BACK: gather buf[pk]∘G ; FWHT bits5-9 ; T2 ; FWHT bits0-4 ; out = S*v + bias
static __device__ __forceinline__ void row_back(const float* __restrict__ bufr,
                                                const int* pk, const float* Gv,
                                                const float* Sv, const float* Biv,
                                                float* tb,
                                                float* __restrict__ outp, int l)
{
    float v[32];
#pragma unroll
    for (int k = 0; k < 32; k++) v[k] = bufr[pk[k]];
#pragma unroll
    for (int k = 0; k < 32; k++) v[k] *= Gv[k];
    fwht32p(v);
    __syncwarp();
#pragma unroll
    for (int k = 0; k < 32; k++) tb[36 * k + l] = v[k];
    __syncwarp();
    {
        const float4* t4 = reinterpret_cast<const float4*>(tb + 36 * l);
#pragma unroll
        for (int q = 0; q < 8; q++) {
            float4 tv = t4[q];
            v[4*q+0] = tv.x; v[4*q+1] = tv.y; v[4*q+2] = tv.z; v[4*q+3] = tv.w;
        }
    }
    fwht32p(v);
    {
        float4* o4 = reinterpret_cast<float4*>(outp);
#pragma unroll
        for (int q = 0; q < 8; q++) {
            float4 ov;
            ov.x = fmaf(Sv[4*q+0], v[4*q+0], Biv[4*q+0]);
            ov.y = fmaf(Sv[4*q+1], v[4*q+1], Biv[4*q+1]);
            ov.z = fmaf(Sv[4*q+2], v[4*q+2], Biv[4*q+2]);
            ov.w = fmaf(Sv[4*q+3], v[4*q+3], Biv[4*q+3]);
            o4[q] = ov;
        }
    }
}

extern "C" __global__ void __launch_bounds__(128, 2)
fastfood_kernel(const float* __restrict__ x,
                const float* __restrict__ B,
                const float* __restrict__ G,
                const float* __restrict__ S,
                const float* __restrict__ bias,
                const int*   __restrict__ P,
                float* __restrict__ out,
                int batch)
{
    // Dynamic shared layout (floats):
    //   [0,4096)        buf0   permute staging, row parity 0
    //   [4096,8192)     buf1   permute staging, row parity 1
    //   [8192,12800)    tbuf   4 warps x 1152 (stride-36 transpose tiles)
    //   [12800,14848)   xbuf   2 x 1024 (double-buffered x row, XOR-swizzled)
    extern __shared__ float smem[];
    float* bufp[2] = { smem, smem + 4096 };
    float* tb      = smem + 8192 + (threadIdx.x >> 5) * 1152;
    float* xb[2]   = { smem + 12800, smem + 12800 + 1024 };

    const int t = threadIdx.x;
    const int l = t & 31;                 // lane
    const int w = t >> 5;                 // warp == stack
    const int a0  = w * 1024 + 32 * l;    // layout-A base
    const int bse = w * 1024 + l;         // layout-B base

    // ---- register-resident weights (once per block; proven 233-reg envelope) ----
    float Bv[32], Sv[32], Biv[32];        // layout A
    float Gv[32];                         // layout B
    int   pk[32];                         // gather addr into swizzled buf
    {
        const float4* B4 = reinterpret_cast<const float4*>(B + a0);
        const float4* S4 = reinterpret_cast<const float4*>(S + a0);
        const float4* b4 = reinterpret_cast<const float4*>(bias + a0);
#pragma unroll
        for (int q = 0; q < 8; q++) {
            float4 tv;
            tv = B4[q]; Bv[4*q+0]=tv.x; Bv[4*q+1]=tv.y; Bv[4*q+2]=tv.z; Bv[4*q+3]=tv.w;
            tv = S4[q]; Sv[4*q+0]=tv.x; Sv[4*q+1]=tv.y; Sv[4*q+2]=tv.z; Sv[4*q+3]=tv.w;
            tv = b4[q]; Biv[4*q+0]=tv.x; Biv[4*q+1]=tv.y; Biv[4*q+2]=tv.z; Biv[4*q+3]=tv.w;
        }
#pragma unroll
        for (int k = 0; k < 32; k++) Gv[k] = G[bse + 32 * k];   // coalesced
#pragma unroll
        for (int k = 0; k < 32; k++) {
            int raw   = P[bse + 32 * k];                 // element in [0,4096)
            int stack = raw >> 10;
            int off   = raw & 1023;
            int iB    = ((off & 31) << 5) | (off >> 5);  // layout-B-linear
            int c     = iB >> 2;                         // float4 chunk
            int p     = c ^ ((c >> 3) & 7);              // XOR swizzle
            pk[k]     = (stack << 10) | (p << 2) | (iB & 3);
        }
    }

    const int row0 = blockIdx.x * ROWS_PER_BLOCK;

    // ---- pipeline prologue ----
    prefetch_x(x, row0, batch, xb[0], t);
    asm volatile("cp.async.wait_group 0;" ::: "memory");
    __syncthreads();                                  // x(0) published
    prefetch_x(x, row0 + 1, batch, xb[1], t);
    row_front(xb[0], Bv, tb, bufp[0] + w * 1024, l);  // stage(0)

#pragma unroll 1
    for (int i = 0; i < ROWS_PER_BLOCK; i++) {
        const int row = row0 + i;

        asm volatile("cp.async.wait_group 0;" ::: "memory");
        __syncthreads();   // publishes stage(i) and x(i+1); retires gathers(i-1)

        if (i + 2 < ROWS_PER_BLOCK)
            prefetch_x(x, row + 2, batch, xb[i & 1], t);     // x(i) consumed

        if (i + 1 < ROWS_PER_BLOCK)
            row_front(xb[(i + 1) & 1], Bv, tb,
                      bufp[(i + 1) & 1] + w * 1024, l);      // stage(i+1)

        if (row < batch)
            row_back(bufp[i & 1], pk, Gv, Sv, Biv, tb,
                     out + (size_t)row * 4096 + a0, l);      // gather/out(i)
    }
}

extern "C" void kernel_launch(void* const* d_in, const int* in_sizes, int n_in,
                              void* d_out, int out_size)
{
    const float* x    = (const float*)d_in[0];   // (16384, 1024) f32
    const float* B    = (const float*)d_in[1];   // (4, 1024) f32
    const float* G    = (const float*)d_in[2];   // (4, 1024) f32
    const float* S    = (const float*)d_in[3];   // (4, 1024) f32
    const float* bias = (const float*)d_in[4];   // (4096,) f32
    const int*   P    = (const int*)d_in[5];     // (4096,) i32
    float* out = (float*)d_out;

    const int batch = in_sizes[0] / 1024;        // 16384

    // 2*4096 (buf) + 4*1152 (tiles) + 2*1024 (xbuf) floats = 58 KB
    const int smem_bytes = (2 * 4096 + 4 * 1152 + 2 * 1024) * (int)sizeof(float);
    cudaFuncSetAttribute(fastfood_kernel,
                         cudaFuncAttributeMaxDynamicSharedMemorySize, smem_bytes);

    const int grid = (batch + ROWS_PER_BLOCK - 1) / ROWS_PER_BLOCK;
    fastfood_kernel<<<grid, 128, smem_bytes>>>(x, B, G, S, bias, P, out, batch);
}